// round 16
// baseline (speedup 1.0000x reference)
#include <cuda_runtime.h>
#include <cuda_fp16.h>
#include <cstdint>

#define MAXN 100000
#define MAXE 1600000
#define DHID 128
#define SCAN_B 1024
#define MAXBLK 128

// ---------------------------------------------------------------------------
// Scratch (device globals; zero-initialized at load; replay-consistent:
// csr_build consumes cnt, fill resets bsums + sync counter)
// ---------------------------------------------------------------------------
__device__ float g_x1[(size_t)MAXN * DHID];
__device__ float g_x2[(size_t)MAXN * DHID];
__device__ int   g_cnt[MAXN];
__device__ int2  g_rc[MAXN];                 // (rowstart, cnt)
__device__ int   g_rank[MAXE];               // per-edge rank within its dst
__device__ int   g_bsums[MAXBLK];            // bit31 = ready flag, bits0..30 = sum
__device__ int   g_sync[1];                  // grid barrier counter
__device__ int2  g_colw[MAXE];               // packed (src, w-bits)
// fp16 weights (hi only), row-major [out 128][k 128]
__device__ unsigned short g_w1h[16384];
__device__ unsigned short g_w2h[16384];

// ---------------------------------------------------------------------------
__device__ __forceinline__ void mma_f16(float* c, const uint32_t* a, const uint32_t* bb) {
    asm volatile(
        "mma.sync.aligned.m16n8k16.row.col.f32.f16.f16.f32 "
        "{%0,%1,%2,%3}, {%4,%5,%6,%7}, {%8,%9}, {%0,%1,%2,%3};"
        : "+f"(c[0]), "+f"(c[1]), "+f"(c[2]), "+f"(c[3])
        : "r"(a[0]), "r"(a[1]), "r"(a[2]), "r"(a[3]), "r"(bb[0]), "r"(bb[1]));
}

__device__ __forceinline__ uint32_t pack_h2(float a, float b, float& ra, float& rb) {
    __half ha = __float2half_rn(a);
    __half hb = __float2half_rn(b);
    ra = a - __half2float(ha);
    rb = b - __half2float(hb);
    return ((uint32_t)__half_as_ushort(hb) << 16) | __half_as_ushort(ha);
}
__device__ __forceinline__ uint32_t pack_h2n(float a, float b) {
    __half ha = __float2half_rn(a);
    __half hb = __float2half_rn(b);
    return ((uint32_t)__half_as_ushort(hb) << 16) | __half_as_ushort(ha);
}

// ---------------------------------------------------------------------------
// Fused CSR build: count (+rank) -> grid flag-barrier -> scan, plus W prep.
// 98 blocks x 1024 threads, all co-resident (98 < 148 SMs) -> spin is safe.
// ---------------------------------------------------------------------------
__global__ void __launch_bounds__(SCAN_B)
csr_build_kernel(const int* __restrict__ dst,
                 const float* __restrict__ w1, const float* __restrict__ w2,
                 int* __restrict__ cnt, int* __restrict__ rank,
                 int* __restrict__ bsums, int* __restrict__ sync_ctr,
                 int2* __restrict__ rc, int N, int E, int nblk) {
    __shared__ int s[SCAN_B];
    __shared__ int boff_sh;
    int tid = threadIdx.x;
    int b = blockIdx.x;
    int gt = b * SCAN_B + tid;
    int gsz = nblk * SCAN_B;

    // ---- W prep (first 32768 threads; independent) ----
    if (gt < 32768) {
        int which = gt >> 14;
        int e = gt & 16383;
        float v = (which ? w2 : w1)[e];
        unsigned short h = __half_as_ushort(__float2half_rn(v));
        if (which) g_w2h[e] = h; else g_w1h[e] = h;
    }

    // ---- phase 1: count + rank (grid-stride) ----
    for (int e = gt; e < E; e += gsz)
        rank[e] = atomicAdd(&cnt[dst[e]], 1);

    // ---- grid barrier ----
    __syncthreads();
    if (tid == 0) {
        __threadfence();
        atomicAdd(sync_ctr, 1);
        while (*((volatile int*)sync_ctr) < nblk) { }
        __threadfence();
    }
    __syncthreads();

    // ---- phase 2: block scan + cross-block offsets (consumes cnt) ----
    int i = gt;
    int v = 0;
    if (i < N) { v = cnt[i]; cnt[i] = 0; }
    s[tid] = v;
    if (tid == 0) boff_sh = 0;
    __syncthreads();
#pragma unroll
    for (int off = 1; off < SCAN_B; off <<= 1) {
        int t = (tid >= off) ? s[tid - off] : 0;
        __syncthreads();
        s[tid] += t;
        __syncthreads();
    }
    if (tid == SCAN_B - 1)
        *((volatile int*)&bsums[b]) = s[tid] | 0x80000000;
    if (tid < b) {
        int bv;
        do { bv = *((volatile int*)&bsums[tid]); } while ((bv & 0x80000000) == 0);
        atomicAdd(&boff_sh, bv & 0x7FFFFFFF);
    }
    __syncthreads();
    if (i < N) {
        int rs = boff_sh + s[tid] - v;
        rc[i] = make_int2(rs, v);
    }
}

// atomic-free fill; also resets bsums + sync counter for the next replay
__global__ void fill_kernel(const int* __restrict__ src, const int* __restrict__ dst,
                            const float* __restrict__ ew,
                            const int2* __restrict__ rc, const int* __restrict__ rank,
                            int2* __restrict__ colw, int* __restrict__ bsums,
                            int* __restrict__ sync_ctr, int E) {
    if (blockIdx.x == 0) {
        if (threadIdx.x < MAXBLK) bsums[threadIdx.x] = 0;
        if (threadIdx.x == 0) *sync_ctr = 0;
    }
    int e = blockIdx.x * blockDim.x + threadIdx.x;
    if (e < E) {
        int d = dst[e];
        int pos = __ldg(&rc[d]).x + rank[e];
        colw[pos] = make_int2(src[e], __float_as_int(ew[e]));
    }
}

// ---------------------------------------------------------------------------
// aggregation + combine:  y = (1+eps)*x + mean over in-edges of x[src]*w
// ---------------------------------------------------------------------------
__global__ void __launch_bounds__(256)
agg_kernel(const float* __restrict__ x,
           const int2* __restrict__ rc, const int2* __restrict__ colw,
           const float* __restrict__ eps_ptr, int eps_idx,
           float* __restrict__ y, int N) {
    int t = blockIdx.x * blockDim.x + threadIdx.x;
    int node = t >> 5;
    int lane = t & 31;
    if (node >= N) return;

    int2 rcv = __ldg(&rc[node]);
    int start = rcv.x;
    int c = rcv.y;

    float4 a0 = make_float4(0.f, 0.f, 0.f, 0.f);
    float4 a1 = a0;
    int j = 0;
    for (; j + 1 < c; j += 2) {
        int2 e0 = __ldg(&colw[start + j]);
        int2 e1 = __ldg(&colw[start + j + 1]);
        float w0 = __int_as_float(e0.y);
        float w1 = __int_as_float(e1.y);
        float4 v0 = __ldg(reinterpret_cast<const float4*>(x + (size_t)e0.x * DHID) + lane);
        float4 v1 = __ldg(reinterpret_cast<const float4*>(x + (size_t)e1.x * DHID) + lane);
        a0.x += v0.x * w0; a0.y += v0.y * w0; a0.z += v0.z * w0; a0.w += v0.w * w0;
        a1.x += v1.x * w1; a1.y += v1.y * w1; a1.z += v1.z * w1; a1.w += v1.w * w1;
    }
    if (j < c) {
        int2 e0 = __ldg(&colw[start + j]);
        float w0 = __int_as_float(e0.y);
        float4 v0 = __ldg(reinterpret_cast<const float4*>(x + (size_t)e0.x * DHID) + lane);
        a0.x += v0.x * w0; a0.y += v0.y * w0; a0.z += v0.z * w0; a0.w += v0.w * w0;
    }
    float dinv = (c > 0) ? (1.0f / (float)c) : 0.0f;
    float epsv = 1.0f + eps_ptr[eps_idx];

    float4 xv = __ldg(reinterpret_cast<const float4*>(x + (size_t)node * DHID + lane * 4));
    float4 o;
    o.x = epsv * xv.x + (a0.x + a1.x) * dinv;
    o.y = epsv * xv.y + (a0.y + a1.y) * dinv;
    o.z = epsv * xv.z + (a0.z + a1.z) * dinv;
    o.w = epsv * xv.w + (a0.w + a1.w) * dinv;
    *reinterpret_cast<float4*>(y + (size_t)node * DHID + lane * 4) = o;
}

// ---------------------------------------------------------------------------
// HMMA GEMM (fp16 2-term):  out = y @ W^T + b  [+relu]
//   A = Ahi + Alo (fp16 split, effectively exact), B = fp16(W)
//   D = Ahi*Bhi + Alo*Bhi
// 128-row blocks, 8 warps, warp tile 32x64 (4 B/HMMA of LDS vs 6 before).
// smem 3x34816 = 104448B -> 2 CTAs/SM.
// ---------------------------------------------------------------------------
#define PADB 272
#define SM_A_HI 0
#define SM_A_LO 34816
#define SM_B    69632
#define SM_TOT  104448

__global__ void __launch_bounds__(256, 2)
mm_kernel(const float* __restrict__ y,
          const unsigned short* __restrict__ wh,
          const float* __restrict__ b,
          float* __restrict__ out, int n_rows, int do_relu, int zero_row0) {
    extern __shared__ __align__(16) char sm[];
    int tid = threadIdx.x;
    int lane = tid & 31;
    int wid = tid >> 5;

    // copy W (128 rows x 128 fp16) into padded smem
    {
        const uint4* bh = reinterpret_cast<const uint4*>(wh);
#pragma unroll
        for (int i = 0; i < 8; i++) {
            int idx = tid + i * 256;
            int row = idx >> 4;
            int c = idx & 15;
            *reinterpret_cast<uint4*>(sm + SM_B + row * PADB + c * 16) = bh[idx];
        }
    }

    // convert A tile (128 rows): y -> fp16 hi/lo
    int row0 = blockIdx.x * 128;
    {
        int r = tid >> 1;               // 0..127
        int kb = (tid & 1) * 64;        // 0 or 64
        int grow = row0 + r;
        bool valid = (grow < n_rows);
        const float4* yp = reinterpret_cast<const float4*>(y + (size_t)grow * 128 + kb);
#pragma unroll
        for (int j = 0; j < 16; j++) {
            float4 v = valid ? __ldg(yp + j) : make_float4(0.f, 0.f, 0.f, 0.f);
            float r0, r1, r2, r3;
            uint2 hp, lp;
            hp.x = pack_h2(v.x, v.y, r0, r1);
            hp.y = pack_h2(v.z, v.w, r2, r3);
            lp.x = pack_h2n(r0, r1);
            lp.y = pack_h2n(r2, r3);
            uint32_t off = (uint32_t)(r * PADB + (kb + j * 4) * 2);
            *reinterpret_cast<uint2*>(sm + SM_A_HI + off) = hp;
            *reinterpret_cast<uint2*>(sm + SM_A_LO + off) = lp;
        }
    }
    __syncthreads();

    int gid = lane >> 2;
    int tig = lane & 3;
    int wr = (wid & 3) * 32;   // warp row base (32 rows)
    int wn = (wid >> 2) * 64;  // warp col base (64 cols)

    const char* pAhi = sm + SM_A_HI + (wr + gid) * PADB + tig * 4;
    const char* pAlo = sm + SM_A_LO + (wr + gid) * PADB + tig * 4;
    const char* pB   = sm + SM_B    + (wn + gid) * PADB + tig * 4;

    float acc[2][8][4];
#pragma unroll
    for (int mt = 0; mt < 2; mt++)
#pragma unroll
        for (int nt = 0; nt < 8; nt++)
#pragma unroll
            for (int q = 0; q < 4; q++) acc[mt][nt][q] = 0.f;

#pragma unroll
    for (int k = 0; k < 8; k++) {
        int ko = k * 32;
        uint32_t ahi[2][4], alo[2][4];
#pragma unroll
        for (int mt = 0; mt < 2; mt++) {
            int mo = mt * 16 * PADB;
            ahi[mt][0] = *reinterpret_cast<const uint32_t*>(pAhi + mo + ko);
            ahi[mt][1] = *reinterpret_cast<const uint32_t*>(pAhi + mo + 8 * PADB + ko);
            ahi[mt][2] = *reinterpret_cast<const uint32_t*>(pAhi + mo + ko + 16);
            ahi[mt][3] = *reinterpret_cast<const uint32_t*>(pAhi + mo + 8 * PADB + ko + 16);
            alo[mt][0] = *reinterpret_cast<const uint32_t*>(pAlo + mo + ko);
            alo[mt][1] = *reinterpret_cast<const uint32_t*>(pAlo + mo + 8 * PADB + ko);
            alo[mt][2] = *reinterpret_cast<const uint32_t*>(pAlo + mo + ko + 16);
            alo[mt][3] = *reinterpret_cast<const uint32_t*>(pAlo + mo + 8 * PADB + ko + 16);
        }
#pragma unroll
        for (int nt = 0; nt < 8; nt++) {
            int no = nt * 8 * PADB;
            uint32_t bh[2];
            bh[0] = *reinterpret_cast<const uint32_t*>(pB + no + ko);
            bh[1] = *reinterpret_cast<const uint32_t*>(pB + no + ko + 16);
#pragma unroll
            for (int mt = 0; mt < 2; mt++) {
                mma_f16(acc[mt][nt], ahi[mt], bh);
                mma_f16(acc[mt][nt], alo[mt], bh);
            }
        }
    }

#pragma unroll
    for (int nt = 0; nt < 8; nt++) {
        int colc = wn + nt * 8 + tig * 2;
        float2 bv = *reinterpret_cast<const float2*>(b + colc);
#pragma unroll
        for (int mt = 0; mt < 2; mt++) {
            int ra = row0 + wr + mt * 16 + gid;
            float2 o0, o1;
            o0.x = acc[mt][nt][0] + bv.x;
            o0.y = acc[mt][nt][1] + bv.y;
            o1.x = acc[mt][nt][2] + bv.x;
            o1.y = acc[mt][nt][3] + bv.y;
            if (do_relu) {
                o0.x = fmaxf(o0.x, 0.f); o0.y = fmaxf(o0.y, 0.f);
                o1.x = fmaxf(o1.x, 0.f); o1.y = fmaxf(o1.y, 0.f);
            }
            if (zero_row0 && ra == 0) { o0.x = 0.f; o0.y = 0.f; }
            if (ra < n_rows)
                *reinterpret_cast<float2*>(out + (size_t)ra * 128 + colc) = o0;
            if (ra + 8 < n_rows)
                *reinterpret_cast<float2*>(out + (size_t)(ra + 8) * 128 + colc) = o1;
        }
    }
}

// ---------------------------------------------------------------------------
extern "C" void kernel_launch(void* const* d_in, const int* in_sizes, int n_in,
                              void* d_out, int out_size) {
    const float* emb    = (const float*)d_in[0];
    const float* w1     = (const float*)d_in[1];
    const float* b1     = (const float*)d_in[2];
    const float* w2     = (const float*)d_in[3];
    const float* b2     = (const float*)d_in[4];
    const float* eps    = (const float*)d_in[5];
    const float* edge_w = (const float*)d_in[6];
    const int*   src    = (const int*)d_in[7];
    const int*   dst    = (const int*)d_in[8];

    int N = in_sizes[0] / DHID;
    int E = in_sizes[6];
    float* out = (float*)d_out;

    float *x1, *x2;
    int *cnt, *bsums, *rank, *sync_ctr;
    int2 *rc, *colw;
    unsigned short *w1h, *w2h;
    cudaGetSymbolAddress((void**)&x1, g_x1);
    cudaGetSymbolAddress((void**)&x2, g_x2);
    cudaGetSymbolAddress((void**)&cnt, g_cnt);
    cudaGetSymbolAddress((void**)&rc, g_rc);
    cudaGetSymbolAddress((void**)&rank, g_rank);
    cudaGetSymbolAddress((void**)&bsums, g_bsums);
    cudaGetSymbolAddress((void**)&sync_ctr, g_sync);
    cudaGetSymbolAddress((void**)&colw, g_colw);
    cudaGetSymbolAddress((void**)&w1h, g_w1h);
    cudaGetSymbolAddress((void**)&w2h, g_w2h);

    static bool attr_set = false;
    if (!attr_set) {
        cudaFuncSetAttribute(mm_kernel,
                             cudaFuncAttributeMaxDynamicSharedMemorySize, SM_TOT);
        attr_set = true;
    }

    int nb = (N + SCAN_B - 1) / SCAN_B;   // 98 blocks, all co-resident
    int g_edges = (E + 255) / 256;
    int g_agg   = ((size_t)N * 32 + 255) / 256;
    int g_mm    = (N + 127) / 128;

    // ---- CSR build + W prep in ONE kernel; fill resets barrier state ----
    csr_build_kernel<<<nb, SCAN_B>>>(dst, w1, w2, cnt, rank, bsums, sync_ctr,
                                     rc, N, E, nb);                         // 1
    fill_kernel<<<g_edges, 256>>>(src, dst, edge_w, rc, rank, colw,
                                  bsums, sync_ctr, E);                      // 2

    // ---- layer 1 ----
    agg_kernel<<<g_agg, 256>>>(emb, rc, colw, eps, 0, x2, N);               // 3
    mm_kernel<<<g_mm, 256, SM_TOT>>>(x2, w1h, b1, x1, N, 1, 0);             // 4 <- ncu

    // ---- layer 2 ----
    agg_kernel<<<g_agg, 256>>>(x1, rc, colw, eps, 1, x2, N);
    mm_kernel<<<g_mm, 256, SM_TOT>>>(x2, w2h, b2, x1, N, 1, 0);

    // ---- layer 3 ----
    agg_kernel<<<g_agg, 256>>>(x1, rc, colw, eps, 2, x2, N);
    mm_kernel<<<g_mm, 256, SM_TOT>>>(x2, w2h, b2, out, N, 0, 1);
}

// round 17
// speedup vs baseline: 1.0109x; 1.0109x over previous
#include <cuda_runtime.h>
#include <cuda_fp16.h>
#include <cstdint>

#define MAXN 100000
#define MAXE 1600000
#define DHID 128
#define SCAN_B 1024
#define MAXBLK 128

// ---------------------------------------------------------------------------
// Scratch (device globals; zero-initialized at load; replay-consistent:
// csr_build consumes cnt, fill resets bsums + sync counter)
// ---------------------------------------------------------------------------
__device__ float g_x1[(size_t)MAXN * DHID];
__device__ float g_x2[(size_t)MAXN * DHID];
__device__ int   g_cnt[MAXN];
__device__ int2  g_rc[MAXN];                 // (rowstart, cnt)
__device__ int   g_rank[MAXE];               // per-edge rank within its dst
__device__ int   g_bsums[MAXBLK];            // bit31 = ready flag, bits0..30 = sum
__device__ int   g_sync[1];                  // grid barrier counter
__device__ __align__(16) int2 g_colw[MAXE];  // packed (src, w-bits), 16B-aligned
// fp16 weights (hi only), row-major [out 128][k 128]
__device__ unsigned short g_w1h[16384];
__device__ unsigned short g_w2h[16384];

// ---------------------------------------------------------------------------
__device__ __forceinline__ void mma_f16(float* c, const uint32_t* a, const uint32_t* bb) {
    asm volatile(
        "mma.sync.aligned.m16n8k16.row.col.f32.f16.f16.f32 "
        "{%0,%1,%2,%3}, {%4,%5,%6,%7}, {%8,%9}, {%0,%1,%2,%3};"
        : "+f"(c[0]), "+f"(c[1]), "+f"(c[2]), "+f"(c[3])
        : "r"(a[0]), "r"(a[1]), "r"(a[2]), "r"(a[3]), "r"(bb[0]), "r"(bb[1]));
}

__device__ __forceinline__ uint32_t pack_h2(float a, float b, float& ra, float& rb) {
    __half ha = __float2half_rn(a);
    __half hb = __float2half_rn(b);
    ra = a - __half2float(ha);
    rb = b - __half2float(hb);
    return ((uint32_t)__half_as_ushort(hb) << 16) | __half_as_ushort(ha);
}
__device__ __forceinline__ uint32_t pack_h2n(float a, float b) {
    __half ha = __float2half_rn(a);
    __half hb = __float2half_rn(b);
    return ((uint32_t)__half_as_ushort(hb) << 16) | __half_as_ushort(ha);
}

// ---------------------------------------------------------------------------
// Fused CSR build: count (+rank) -> grid flag-barrier -> scan, plus W prep.
// 98 blocks x 1024 threads, all co-resident (98 < 148 SMs) -> spin is safe.
// ---------------------------------------------------------------------------
__global__ void __launch_bounds__(SCAN_B)
csr_build_kernel(const int* __restrict__ dst,
                 const float* __restrict__ w1, const float* __restrict__ w2,
                 int* __restrict__ cnt, int* __restrict__ rank,
                 int* __restrict__ bsums, int* __restrict__ sync_ctr,
                 int2* __restrict__ rc, int N, int E, int nblk) {
    __shared__ int s[SCAN_B];
    __shared__ int boff_sh;
    int tid = threadIdx.x;
    int b = blockIdx.x;
    int gt = b * SCAN_B + tid;
    int gsz = nblk * SCAN_B;

    // ---- W prep (first 32768 threads; independent) ----
    if (gt < 32768) {
        int which = gt >> 14;
        int e = gt & 16383;
        float v = (which ? w2 : w1)[e];
        unsigned short h = __half_as_ushort(__float2half_rn(v));
        if (which) g_w2h[e] = h; else g_w1h[e] = h;
    }

    // ---- phase 1: count + rank (grid-stride) ----
    for (int e = gt; e < E; e += gsz)
        rank[e] = atomicAdd(&cnt[dst[e]], 1);

    // ---- grid barrier ----
    __syncthreads();
    if (tid == 0) {
        __threadfence();
        atomicAdd(sync_ctr, 1);
        while (*((volatile int*)sync_ctr) < nblk) { }
        __threadfence();
    }
    __syncthreads();

    // ---- phase 2: block scan + cross-block offsets (consumes cnt) ----
    int i = gt;
    int v = 0;
    if (i < N) { v = cnt[i]; cnt[i] = 0; }
    s[tid] = v;
    if (tid == 0) boff_sh = 0;
    __syncthreads();
#pragma unroll
    for (int off = 1; off < SCAN_B; off <<= 1) {
        int t = (tid >= off) ? s[tid - off] : 0;
        __syncthreads();
        s[tid] += t;
        __syncthreads();
    }
    if (tid == SCAN_B - 1)
        *((volatile int*)&bsums[b]) = s[tid] | 0x80000000;
    if (tid < b) {
        int bv;
        do { bv = *((volatile int*)&bsums[tid]); } while ((bv & 0x80000000) == 0);
        atomicAdd(&boff_sh, bv & 0x7FFFFFFF);
    }
    __syncthreads();
    if (i < N) {
        int rs = boff_sh + s[tid] - v;
        rc[i] = make_int2(rs, v);
    }
}

// atomic-free fill; also resets bsums + sync counter for the next replay
__global__ void fill_kernel(const int* __restrict__ src, const int* __restrict__ dst,
                            const float* __restrict__ ew,
                            const int2* __restrict__ rc, const int* __restrict__ rank,
                            int2* __restrict__ colw, int* __restrict__ bsums,
                            int* __restrict__ sync_ctr, int E) {
    if (blockIdx.x == 0) {
        if (threadIdx.x < MAXBLK) bsums[threadIdx.x] = 0;
        if (threadIdx.x == 0) *sync_ctr = 0;
    }
    int e = blockIdx.x * blockDim.x + threadIdx.x;
    if (e < E) {
        int d = dst[e];
        int pos = __ldg(&rc[d]).x + rank[e];
        colw[pos] = make_int2(src[e], __float_as_int(ew[e]));
    }
}

// ---------------------------------------------------------------------------
// aggregation + combine:  y = (1+eps)*x + mean over in-edges of x[src]*w
// one warp per node; lane owns 4 features. Edge pairs loaded as one aligned
// LDG.128 (odd start peeled) -> halves edge-list load instructions.
// ---------------------------------------------------------------------------
__global__ void __launch_bounds__(256)
agg_kernel(const float* __restrict__ x,
           const int2* __restrict__ rc, const int2* __restrict__ colw,
           const float* __restrict__ eps_ptr, int eps_idx,
           float* __restrict__ y, int N) {
    int t = blockIdx.x * blockDim.x + threadIdx.x;
    int node = t >> 5;
    int lane = t & 31;
    if (node >= N) return;

    int2 rcv = __ldg(&rc[node]);
    int j = rcv.x;
    int end = rcv.x + rcv.y;
    int c = rcv.y;

    float4 a0 = make_float4(0.f, 0.f, 0.f, 0.f);
    float4 a1 = a0;

    // peel one edge if start is odd (align to 16B for int4 loads)
    if ((j & 1) && j < end) {
        int2 e0 = __ldg(&colw[j]);
        float w0 = __int_as_float(e0.y);
        float4 v0 = __ldg(reinterpret_cast<const float4*>(x + (size_t)e0.x * DHID) + lane);
        a0.x += v0.x * w0; a0.y += v0.y * w0; a0.z += v0.z * w0; a0.w += v0.w * w0;
        j++;
    }
    for (; j + 1 < end; j += 2) {
        int4 ee = __ldg(reinterpret_cast<const int4*>(&colw[j]));   // 2 edges, 1 LDG.128
        float w0 = __int_as_float(ee.y);
        float w1 = __int_as_float(ee.w);
        float4 v0 = __ldg(reinterpret_cast<const float4*>(x + (size_t)ee.x * DHID) + lane);
        float4 v1 = __ldg(reinterpret_cast<const float4*>(x + (size_t)ee.z * DHID) + lane);
        a0.x += v0.x * w0; a0.y += v0.y * w0; a0.z += v0.z * w0; a0.w += v0.w * w0;
        a1.x += v1.x * w1; a1.y += v1.y * w1; a1.z += v1.z * w1; a1.w += v1.w * w1;
    }
    if (j < end) {
        int2 e0 = __ldg(&colw[j]);
        float w0 = __int_as_float(e0.y);
        float4 v0 = __ldg(reinterpret_cast<const float4*>(x + (size_t)e0.x * DHID) + lane);
        a0.x += v0.x * w0; a0.y += v0.y * w0; a0.z += v0.z * w0; a0.w += v0.w * w0;
    }

    float dinv = (c > 0) ? (1.0f / (float)c) : 0.0f;
    float epsv = 1.0f + eps_ptr[eps_idx];

    float4 xv = __ldg(reinterpret_cast<const float4*>(x + (size_t)node * DHID + lane * 4));
    float4 o;
    o.x = epsv * xv.x + (a0.x + a1.x) * dinv;
    o.y = epsv * xv.y + (a0.y + a1.y) * dinv;
    o.z = epsv * xv.z + (a0.z + a1.z) * dinv;
    o.w = epsv * xv.w + (a0.w + a1.w) * dinv;
    *reinterpret_cast<float4*>(y + (size_t)node * DHID + lane * 4) = o;
}

// ---------------------------------------------------------------------------
// HMMA GEMM (fp16 2-term, R15-exact):  out = y @ W^T + b  [+relu]
//   A = Ahi + Alo (fp16 split, effectively exact), B = fp16(W)
//   D = Ahi*Bhi + Alo*Bhi
// 64-row tiles; smem 69632B -> 3 CTAs/SM (proven best: 44.6us).
// ---------------------------------------------------------------------------
#define PADB 272
#define SM_A_HI 0
#define SM_A_LO 17408
#define SM_B    34816
#define SM_TOT  69632

__global__ void __launch_bounds__(256, 3)
mm_kernel(const float* __restrict__ y,
          const unsigned short* __restrict__ wh,
          const float* __restrict__ b,
          float* __restrict__ out, int n_rows, int do_relu, int zero_row0) {
    extern __shared__ __align__(16) char sm[];
    int tid = threadIdx.x;
    int lane = tid & 31;
    int wid = tid >> 5;

    // copy W hi (128 rows x 128 fp16) into padded smem
    {
        const uint4* bh = reinterpret_cast<const uint4*>(wh);
#pragma unroll
        for (int i = 0; i < 8; i++) {
            int idx = tid + i * 256;
            int row = idx >> 4;
            int c = idx & 15;
            *reinterpret_cast<uint4*>(sm + SM_B + row * PADB + c * 16) = bh[idx];
        }
    }

    int row0 = blockIdx.x * 64;
    {
        int r = tid >> 2;               // 0..63
        int kb = (tid & 3) * 32;        // 0,32,64,96
        int grow = row0 + r;
        bool valid = (grow < n_rows);
        const float4* yp = reinterpret_cast<const float4*>(y + (size_t)grow * 128 + kb);
#pragma unroll
        for (int j = 0; j < 8; j++) {
            float4 v = valid ? __ldg(yp + j) : make_float4(0.f, 0.f, 0.f, 0.f);
            float r0, r1, r2, r3;
            uint2 hp, lp;
            hp.x = pack_h2(v.x, v.y, r0, r1);
            hp.y = pack_h2(v.z, v.w, r2, r3);
            lp.x = pack_h2n(r0, r1);
            lp.y = pack_h2n(r2, r3);
            uint32_t off = (uint32_t)(r * PADB + (kb + j * 4) * 2);
            *reinterpret_cast<uint2*>(sm + SM_A_HI + off) = hp;
            *reinterpret_cast<uint2*>(sm + SM_A_LO + off) = lp;
        }
    }
    __syncthreads();

    int gid = lane >> 2;
    int tig = lane & 3;
    int wr = (wid & 3) * 16;   // warp row base
    int wn = (wid >> 2) * 64;  // warp col base

    const char* pAhi = sm + SM_A_HI + (wr + gid) * PADB + tig * 4;
    const char* pAlo = sm + SM_A_LO + (wr + gid) * PADB + tig * 4;
    const char* pB   = sm + SM_B    + (wn + gid) * PADB + tig * 4;

    float acc[8][4];
#pragma unroll
    for (int nt = 0; nt < 8; nt++)
#pragma unroll
        for (int q = 0; q < 4; q++) acc[nt][q] = 0.f;

#pragma unroll
    for (int k = 0; k < 8; k++) {
        int ko = k * 32;
        uint32_t ahi[4], alo[4];
        ahi[0] = *reinterpret_cast<const uint32_t*>(pAhi + ko);
        ahi[1] = *reinterpret_cast<const uint32_t*>(pAhi + 8 * PADB + ko);
        ahi[2] = *reinterpret_cast<const uint32_t*>(pAhi + ko + 16);
        ahi[3] = *reinterpret_cast<const uint32_t*>(pAhi + 8 * PADB + ko + 16);
        alo[0] = *reinterpret_cast<const uint32_t*>(pAlo + ko);
        alo[1] = *reinterpret_cast<const uint32_t*>(pAlo + 8 * PADB + ko);
        alo[2] = *reinterpret_cast<const uint32_t*>(pAlo + ko + 16);
        alo[3] = *reinterpret_cast<const uint32_t*>(pAlo + 8 * PADB + ko + 16);
#pragma unroll
        for (int nt = 0; nt < 8; nt++) {
            int no = nt * 8 * PADB;
            uint32_t bh[2];
            bh[0] = *reinterpret_cast<const uint32_t*>(pB + no + ko);
            bh[1] = *reinterpret_cast<const uint32_t*>(pB + no + ko + 16);
            mma_f16(acc[nt], ahi, bh);
            mma_f16(acc[nt], alo, bh);
        }
    }

#pragma unroll
    for (int nt = 0; nt < 8; nt++) {
        int colc = wn + nt * 8 + tig * 2;
        float2 bv = *reinterpret_cast<const float2*>(b + colc);
        int ra = row0 + wr + gid;
        float2 o0, o1;
        o0.x = acc[nt][0] + bv.x;
        o0.y = acc[nt][1] + bv.y;
        o1.x = acc[nt][2] + bv.x;
        o1.y = acc[nt][3] + bv.y;
        if (do_relu) {
            o0.x = fmaxf(o0.x, 0.f); o0.y = fmaxf(o0.y, 0.f);
            o1.x = fmaxf(o1.x, 0.f); o1.y = fmaxf(o1.y, 0.f);
        }
        if (zero_row0 && ra == 0) { o0.x = 0.f; o0.y = 0.f; }
        if (ra < n_rows)
            *reinterpret_cast<float2*>(out + (size_t)ra * 128 + colc) = o0;
        if (ra + 8 < n_rows)
            *reinterpret_cast<float2*>(out + (size_t)(ra + 8) * 128 + colc) = o1;
    }
}

// ---------------------------------------------------------------------------
extern "C" void kernel_launch(void* const* d_in, const int* in_sizes, int n_in,
                              void* d_out, int out_size) {
    const float* emb    = (const float*)d_in[0];
    const float* w1     = (const float*)d_in[1];
    const float* b1     = (const float*)d_in[2];
    const float* w2     = (const float*)d_in[3];
    const float* b2     = (const float*)d_in[4];
    const float* eps    = (const float*)d_in[5];
    const float* edge_w = (const float*)d_in[6];
    const int*   src    = (const int*)d_in[7];
    const int*   dst    = (const int*)d_in[8];

    int N = in_sizes[0] / DHID;
    int E = in_sizes[6];
    float* out = (float*)d_out;

    float *x1, *x2;
    int *cnt, *bsums, *rank, *sync_ctr;
    int2 *rc, *colw;
    unsigned short *w1h, *w2h;
    cudaGetSymbolAddress((void**)&x1, g_x1);
    cudaGetSymbolAddress((void**)&x2, g_x2);
    cudaGetSymbolAddress((void**)&cnt, g_cnt);
    cudaGetSymbolAddress((void**)&rc, g_rc);
    cudaGetSymbolAddress((void**)&rank, g_rank);
    cudaGetSymbolAddress((void**)&bsums, g_bsums);
    cudaGetSymbolAddress((void**)&sync_ctr, g_sync);
    cudaGetSymbolAddress((void**)&colw, g_colw);
    cudaGetSymbolAddress((void**)&w1h, g_w1h);
    cudaGetSymbolAddress((void**)&w2h, g_w2h);

    static bool attr_set = false;
    if (!attr_set) {
        cudaFuncSetAttribute(mm_kernel,
                             cudaFuncAttributeMaxDynamicSharedMemorySize, SM_TOT);
        attr_set = true;
    }

    int nb = (N + SCAN_B - 1) / SCAN_B;   // 98 blocks, all co-resident
    int g_edges = (E + 255) / 256;
    int g_agg   = ((size_t)N * 32 + 255) / 256;
    int g_mm    = (N + 63) / 64;

    // ---- CSR build + W prep in ONE kernel; fill resets barrier state ----
    csr_build_kernel<<<nb, SCAN_B>>>(dst, w1, w2, cnt, rank, bsums, sync_ctr,
                                     rc, N, E, nb);                         // 1
    fill_kernel<<<g_edges, 256>>>(src, dst, edge_w, rc, rank, colw,
                                  bsums, sync_ctr, E);                      // 2

    // ---- layer 1 ----
    agg_kernel<<<g_agg, 256>>>(emb, rc, colw, eps, 0, x2, N);               // 3
    mm_kernel<<<g_mm, 256, SM_TOT>>>(x2, w1h, b1, x1, N, 1, 0);             // 4 <- ncu

    // ---- layer 2 ----
    agg_kernel<<<g_agg, 256>>>(x1, rc, colw, eps, 1, x2, N);
    mm_kernel<<<g_mm, 256, SM_TOT>>>(x2, w2h, b2, x1, N, 1, 0);

    // ---- layer 3 ----
    agg_kernel<<<g_agg, 256>>>(x1, rc, colw, eps, 2, x2, N);
    mm_kernel<<<g_mm, 256, SM_TOT>>>(x2, w2h, b2, out, N, 0, 1);
}